// round 12
// baseline (speedup 1.0000x reference)
#include <cuda_runtime.h>

#define POOLK 7
#define NBINS (POOLK * POOLK)
#define NUM_ROIS 300
#define FH 50
#define FW 50
#define FC 512
#define NPIX (FH * FW)
#define NBIN_TOT (NUM_ROIS * NBINS)            // 14700
#define TOTAL_F4 (NBIN_TOT * (FC / 4))         // 1,881,600
#define WBLOCKS 1184                            // 148 SMs * 8 CTAs: one wave
#define WSTRIDE (WBLOCKS * 256)                 // 303,104
#define WFULL (TOTAL_F4 / WSTRIDE)              // 6 full strided iters

// Scratch (no cudaMalloc allowed)
__device__ float g_fmax[NPIX];
__device__ float g_binmax[NBIN_TOT];

// K1: one block of 128 threads per pixel (best measured config: 4.67us).
__global__ void fmax_kernel(const float* __restrict__ fm) {
    __shared__ float smem[4];
    int pix = blockIdx.x;
    int tid = threadIdx.x;
    float4 v = reinterpret_cast<const float4*>(fm + (size_t)pix * FC)[tid];
    float m = fmaxf(fmaxf(v.x, v.y), fmaxf(v.z, v.w));
#pragma unroll
    for (int off = 16; off > 0; off >>= 1)
        m = fmaxf(m, __shfl_xor_sync(0xffffffffu, m, off));
    if ((tid & 31) == 0) smem[tid >> 5] = m;
    __syncthreads();
    if (tid == 0)
        g_fmax[pix] = fmaxf(fmaxf(smem[0], smem[1]), fmaxf(smem[2], smem[3]));
}

// K2: one thread per (roi, bin); fmax map staged in smem, independent loads.
__global__ void __launch_bounds__(256) binmax_kernel(
    const float* __restrict__ rois) {
    __shared__ float sf[NPIX];
    int tid = threadIdx.x;
    for (int k = tid; k < NPIX; k += 256) sf[k] = g_fmax[k];
    __syncthreads();

    int idx = blockIdx.x * 256 + tid;
    if (idx >= NBIN_TOT) return;

    int r = idx / NBINS;
    int bin = idx - r * NBINS;
    int i = bin / POOLK;
    int j = bin - i * POOLK;

    const float* roi = rois + r * 5;
    // reference: (rois * (1/16)).astype(int32) -> truncation; inputs >= 0
    int x1 = (int)(__ldg(roi + 1) * 0.0625f);
    int y1 = (int)(__ldg(roi + 2) * 0.0625f);
    int x2 = (int)(__ldg(roi + 3) * 0.0625f);
    int y2 = (int)(__ldg(roi + 4) * 0.0625f);
    int rh = y2 - y1 + 1;
    int rw = x2 - x1 + 1;

    int hs = min(max(y1 + (i * rh) / POOLK, 0), FH);
    int he = min(max(y1 + ((i + 1) * rh + POOLK - 1) / POOLK, 0), FH);
    int ws = min(max(x1 + (j * rw) / POOLK, 0), FW);
    int we = min(max(x1 + ((j + 1) * rw + POOLK - 1) / POOLK, 0), FW);

    float m = -INFINITY;
    for (int y = hs; y < he; y++) {
        const float* row = sf + y * FW;
        for (int x = ws; x < we; x++)
            m = fmaxf(m, row[x]);
    }
    g_binmax[idx] = m;
}

// K3: ONE-WAVE grid-stride write. 1184 blocks x 256 threads; each thread
// does 6 (+1 tail) independent LDG->STG.128 pairs, fully unrolled (MLP=6).
// k>>7 is warp-uniform (stride is a multiple of 128) -> broadcast loads.
__global__ void __launch_bounds__(256) write_kernel(float* __restrict__ out) {
    int t0 = blockIdx.x * 256 + threadIdx.x;
    float4* o = reinterpret_cast<float4*>(out);
    float v[WFULL];
#pragma unroll
    for (int i = 0; i < WFULL; i++)
        v[i] = __ldg(&g_binmax[(t0 + i * WSTRIDE) >> 7]);
#pragma unroll
    for (int i = 0; i < WFULL; i++)
        o[t0 + i * WSTRIDE] = make_float4(v[i], v[i], v[i], v[i]);
    int k = t0 + WFULL * WSTRIDE;
    if (k < TOTAL_F4) {
        float w = __ldg(&g_binmax[k >> 7]);
        o[k] = make_float4(w, w, w, w);
    }
}

extern "C" void kernel_launch(void* const* d_in, const int* in_sizes, int n_in,
                              void* d_out, int out_size) {
    const float* rois = (const float*)d_in[0];          // (300, 5)
    const float* feature_maps = (const float*)d_in[1];  // (50, 50, 512)
    float* out = (float*)d_out;                         // (300, 7, 7, 512)

    fmax_kernel<<<NPIX, 128>>>(feature_maps);
    binmax_kernel<<<(NBIN_TOT + 255) / 256, 256>>>(rois);
    write_kernel<<<WBLOCKS, 256>>>(out);
}

// round 13
// speedup vs baseline: 1.3409x; 1.3409x over previous
#include <cuda_runtime.h>
#include <cstdint>

#define POOLK 7
#define NBINS (POOLK * POOLK)
#define NUM_ROIS 300
#define FH 50
#define FW 50
#define FC 512
#define NPIX (FH * FW)
#define NBIN_TOT (NUM_ROIS * NBINS)      // 14700
#define BINS_PER_BLK 12                   // 14700/12 = 1225 CTAs
#define SLAB_F4 (BINS_PER_BLK * FC / 4)   // 1536 float4 = 24 KB
#define SLAB_BYTES (SLAB_F4 * 16)         // 24576

// Scratch (no cudaMalloc allowed)
__device__ float g_fmax[NPIX];

__device__ __forceinline__ uint32_t smem_u32(const void* p) {
    uint32_t a;
    asm("{ .reg .u64 t; cvta.to.shared.u64 t, %1; cvt.u32.u64 %0, t; }"
        : "=r"(a) : "l"(p));
    return a;
}

// K1: one warp per pixel, channel-max over 512 floats (MLP=4/thread).
__global__ void fmax_kernel(const float* __restrict__ fm) {
    int warp = (blockIdx.x * blockDim.x + threadIdx.x) >> 5;
    int lane = threadIdx.x & 31;
    if (warp >= NPIX) return;
    const float4* p = reinterpret_cast<const float4*>(fm + (size_t)warp * FC);
    float m = -INFINITY;
#pragma unroll
    for (int k = 0; k < 4; k++) {
        float4 v = p[lane + 32 * k];
        m = fmaxf(m, fmaxf(fmaxf(v.x, v.y), fmaxf(v.z, v.w)));
    }
#pragma unroll
    for (int off = 16; off > 0; off >>= 1)
        m = fmaxf(m, __shfl_xor_sync(0xffffffffu, m, off));
    if (lane == 0) g_fmax[warp] = m;
}

// K2: one CTA per 12 consecutive bins.
//   Phase A: threads 0..11 each reduce one bin (<=64 independent L2 loads).
//   Phase B: build the 24KB output slab in smem (6 STS.128/thread),
//            then ONE TMA bulk store smem->gmem per CTA.
__global__ void __launch_bounds__(256) roi_tma_kernel(
    const float* __restrict__ rois, float* __restrict__ out) {
    __shared__ float4 slab[SLAB_F4];          // 24 KB
    __shared__ float sbin[BINS_PER_BLK];
    int tid = threadIdx.x;
    int bin0 = blockIdx.x * BINS_PER_BLK;

    if (tid < BINS_PER_BLK) {
        int idx = bin0 + tid;
        int r = idx / NBINS;
        int bin = idx - r * NBINS;
        int i = bin / POOLK;
        int j = bin - i * POOLK;

        const float* roi = rois + r * 5;
        // reference: (rois * (1/16)).astype(int32) -> truncation; inputs >= 0
        int x1 = (int)(__ldg(roi + 1) * 0.0625f);
        int y1 = (int)(__ldg(roi + 2) * 0.0625f);
        int x2 = (int)(__ldg(roi + 3) * 0.0625f);
        int y2 = (int)(__ldg(roi + 4) * 0.0625f);
        int rh = y2 - y1 + 1;
        int rw = x2 - x1 + 1;

        int hs = min(max(y1 + (i * rh) / POOLK, 0), FH);
        int he = min(max(y1 + ((i + 1) * rh + POOLK - 1) / POOLK, 0), FH);
        int ws = min(max(x1 + (j * rw) / POOLK, 0), FW);
        int we = min(max(x1 + ((j + 1) * rw + POOLK - 1) / POOLK, 0), FW);

        float m = -INFINITY;
        for (int y = hs; y < he; y++) {
            const float* row = g_fmax + y * FW;
#pragma unroll 8
            for (int x = ws; x < we; x++)
                m = fmaxf(m, __ldg(row + x));
        }
        sbin[tid] = m;
    }
    __syncthreads();

    // Build slab: f4 index k = tid + i*256; bin = k>>7 = 2i + (tid>>7),
    // warp-uniform -> LDS broadcast.
    int hi = tid >> 7;
#pragma unroll
    for (int i = 0; i < SLAB_F4 / 256; i++) {
        float v = sbin[2 * i + hi];
        slab[i * 256 + tid] = make_float4(v, v, v, v);
    }
    __syncthreads();

    // One bulk async store of the whole 24KB slab.
    if (tid == 0) {
        asm volatile("fence.proxy.async.shared::cta;" ::: "memory");
        uint64_t gdst = (uint64_t)(out + (size_t)bin0 * FC);
        uint32_t ssrc = smem_u32(slab);
        asm volatile(
            "cp.async.bulk.global.shared::cta.bulk_group [%0], [%1], %2;"
            :: "l"(gdst), "r"(ssrc), "n"(SLAB_BYTES) : "memory");
        asm volatile("cp.async.bulk.commit_group;" ::: "memory");
        asm volatile("cp.async.bulk.wait_group 0;" ::: "memory");
    }
    __syncthreads();   // keep smem alive until the bulk copy has read it
}

extern "C" void kernel_launch(void* const* d_in, const int* in_sizes, int n_in,
                              void* d_out, int out_size) {
    const float* rois = (const float*)d_in[0];          // (300, 5)
    const float* feature_maps = (const float*)d_in[1];  // (50, 50, 512)
    float* out = (float*)d_out;                         // (300, 7, 7, 512)

    fmax_kernel<<<(NPIX * 32 + 255) / 256, 256>>>(feature_maps);
    roi_tma_kernel<<<NBIN_TOT / BINS_PER_BLK, 256>>>(rois, out);
}